// round 12
// baseline (speedup 1.0000x reference)
#include <cuda_runtime.h>
#include <cuda_fp16.h>
#include <cstdint>

#define M_TOTAL 8192
#define IN_F    4096
#define OUT_F   4096
#define RANK    64
#define KSPLIT  8
#define MQ      2048      // M quarter

// ---------------- device scratch ----------------
__device__ __align__(16) __half g_Tp[KSPLIT * M_TOTAL * RANK]; // partials fp16
__device__ __align__(16) __half g_T[M_TOTAL * RANK];           // reduced fp16
__device__ __align__(16) __half g_U[OUT_F * RANK];             // fp16
__device__ __align__(16) __half g_V[IN_F * RANK];              // fp16

// ---------------- helpers ----------------
__device__ __forceinline__ uint32_t smem_u32(const void* p) {
    uint32_t a;
    asm("{ .reg .u64 t; cvta.to.shared.u64 t, %1; cvt.u32.u64 %0, t; }" : "=r"(a) : "l"(p));
    return a;
}
#define SWZ(o) ((o) ^ (((o) >> 3) & 0x70))

__device__ __forceinline__ void cpasync16(uint32_t dst, const void* src) {
    asm volatile("cp.async.cg.shared.global [%0], [%1], 16;"
                 :: "r"(dst), "l"(__cvta_generic_to_global(src)) : "memory");
}
#define CP_COMMIT() asm volatile("cp.async.commit_group;" ::: "memory")
#define CP_WAIT0()  asm volatile("cp.async.wait_group 0;" ::: "memory")

__device__ __forceinline__ void ldmx4(uint32_t* r, uint32_t addr) {
    asm volatile("ldmatrix.sync.aligned.m8n8.x4.shared.b16 {%0,%1,%2,%3}, [%4];"
                 : "=r"(r[0]), "=r"(r[1]), "=r"(r[2]), "=r"(r[3]) : "r"(addr));
}
__device__ __forceinline__ void ldmx4t(uint32_t* r, uint32_t addr) {
    asm volatile("ldmatrix.sync.aligned.m8n8.x4.trans.shared.b16 {%0,%1,%2,%3}, [%4];"
                 : "=r"(r[0]), "=r"(r[1]), "=r"(r[2]), "=r"(r[3]) : "r"(addr));
}
__device__ __forceinline__ void mma_f16(float* d, const uint32_t* a, const uint32_t* b) {
    asm volatile(
        "mma.sync.aligned.m16n8k16.row.col.f32.f16.f16.f32 "
        "{%0,%1,%2,%3}, {%4,%5,%6,%7}, {%8,%9}, {%0,%1,%2,%3};"
        : "+f"(d[0]), "+f"(d[1]), "+f"(d[2]), "+f"(d[3])
        : "r"(a[0]), "r"(a[1]), "r"(a[2]), "r"(a[3]), "r"(b[0]), "r"(b[1]));
}
__device__ __forceinline__ uint2 pack4h(const float4& a) {
    __half2 h0 = __floats2half2_rn(a.x, a.y);
    __half2 h1 = __floats2half2_rn(a.z, a.w);
    return make_uint2(*(uint32_t*)&h0, *(uint32_t*)&h1);
}

// ========================================================================
// Kernel 0: convert U, V -> fp16
// ========================================================================
__global__ void __launch_bounds__(256) k0_prep(const float* __restrict__ U,
                                               const float* __restrict__ V) {
    int t = blockIdx.x * 256 + threadIdx.x;
    size_t off = (size_t)t * 4;
    {
        float4 a = __ldg((const float4*)(U + off));
        *(uint2*)(g_U + off) = pack4h(a);
    }
    {
        float4 a = __ldg((const float4*)(V + off));
        *(uint2*)(g_V + off) = pack4h(a);
    }
}

// ========================================================================
// path: k1 (round-8 proven) — Tp[ksp] for one [128M,64N] tile
// ========================================================================
static constexpr int S1_A = 0, S1_B = 16384;
static constexpr int S1_STAGE = 24576;
static constexpr int SM_FUSED = 49152;           // max of paths

__device__ void k1_path(const float* __restrict__ x, int bid, int mq,
                        char* smem) {
    const uint32_t sb = smem_u32(smem);
    const int tid  = threadIdx.x;
    const int lane = tid & 31;
    const int wid  = tid >> 5;
    const int wm   = wid >> 1;
    const int wn   = wid & 1;
    const int m0   = mq * MQ + (bid >> 3) * 128;
    const int ksp  = bid & 7;
    const int k0   = ksp * (IN_F / KSPLIT);

    const int sub = lane >> 3, lr = lane & 7;
    uint32_t a_off[2];
    #pragma unroll
    for (int mt = 0; mt < 2; mt++)
        a_off[mt] = (uint32_t)((wm * 32 + mt * 16 + (sub & 1) * 8 + lr) * 128 + (sub >> 1) * 16);
    const uint32_t bt_off = (uint32_t)(((sub & 1) * 8 + lr) * 128 + wn * 64 + (sub >> 1) * 16);

    float acc[2][4][4];
    #pragma unroll
    for (int mt = 0; mt < 2; mt++)
        #pragma unroll
        for (int j = 0; j < 4; j++)
            #pragma unroll
            for (int t = 0; t < 4; t++) acc[mt][j][t] = 0.0f;

    float4 xa[8];

    auto ldg_x = [&](int c) {
        #pragma unroll
        for (int i = 0; i < 8; i++) {
            int idx = tid + i * 256;
            int r = idx >> 4, q = idx & 15;
            xa[i] = __ldg((const float4*)(x + (size_t)(m0 + r) * IN_F + k0 + c * 64 + q * 4));
        }
    };
    auto sts_x = [&](int stg) {
        char* st = smem + stg * S1_STAGE;
        #pragma unroll
        for (int i = 0; i < 8; i++) {
            int idx = tid + i * 256;
            int r = idx >> 4, q = idx & 15;
            *(uint2*)(st + S1_A + SWZ((uint32_t)(r * 128 + q * 8))) = pack4h(xa[i]);
        }
    };
    auto cp_v = [&](int c, int stg) {
        uint32_t dst = sb + stg * S1_STAGE + S1_B;
        #pragma unroll
        for (int i = 0; i < 2; i++) {
            int idx = tid + i * 256;
            int r = idx >> 3, g = idx & 7;
            cpasync16(dst + SWZ((uint32_t)(r * 128 + g * 16)),
                      (const char*)g_V + (size_t)(k0 + c * 64 + r) * 128 + g * 16);
        }
        CP_COMMIT();
    };

    const int NCHUNK = (IN_F / KSPLIT) / 64;     // 8

    cp_v(0, 0);
    ldg_x(0);
    sts_x(0);
    CP_WAIT0();
    __syncthreads();

    for (int c = 0; c < NCHUNK; c++) {
        const int buf = c & 1;
        const int nbuf = buf ^ 1;

        if (c + 1 < NCHUNK) {
            cp_v(c + 1, nbuf);
            ldg_x(c + 1);
        }

        const uint32_t sbuf = sb + buf * S1_STAGE;
        #pragma unroll
        for (int ks = 0; ks < 4; ks++) {
            uint32_t a[2][4], b[8];
            #pragma unroll
            for (int mt = 0; mt < 2; mt++)
                ldmx4(a[mt], sbuf + S1_A + SWZ(a_off[mt] + ks * 32));
            ldmx4t(b,     sbuf + S1_B + SWZ(bt_off + ks * 16 * 128));
            ldmx4t(b + 4, sbuf + S1_B + SWZ(bt_off + ks * 16 * 128 + 32));
            #pragma unroll
            for (int mt = 0; mt < 2; mt++)
                #pragma unroll
                for (int j = 0; j < 4; j++)
                    mma_f16(acc[mt][j], a[mt], b + 2 * j);
        }

        if (c + 1 < NCHUNK) {
            sts_x(nbuf);
            CP_WAIT0();
        }
        __syncthreads();
    }

    __half* Tp = g_Tp + (size_t)ksp * (M_TOTAL * RANK);
    const int gq = lane >> 2, tig = lane & 3;
    #pragma unroll
    for (int mt = 0; mt < 2; mt++) {
        #pragma unroll
        for (int j = 0; j < 4; j++) {
            int col  = wn * 32 + j * 8 + tig * 2;
            int row0 = m0 + wm * 32 + mt * 16 + gq;
            *(__half2*)(Tp + (size_t)row0 * RANK + col) =
                __floats2half2_rn(acc[mt][j][0], acc[mt][j][1]);
            *(__half2*)(Tp + (size_t)(row0 + 8) * RANK + col) =
                __floats2half2_rn(acc[mt][j][2], acc[mt][j][3]);
        }
    }
}

// ========================================================================
// path: k1r — reduce one quarter
// ========================================================================
__device__ void k1r_path(int bid, int mq) {
    int t = bid * 256 + threadIdx.x;             // 0..16383
    size_t off = (size_t)mq * (MQ * RANK) + (size_t)t * 8;
    float2 s[4] = {{0,0},{0,0},{0,0},{0,0}};
    #pragma unroll
    for (int p = 0; p < KSPLIT; p++) {
        uint4 v = *(const uint4*)(g_Tp + (size_t)p * (M_TOTAL * RANK) + off);
        const __half2* h = (const __half2*)&v;
        #pragma unroll
        for (int q = 0; q < 4; q++) {
            float2 f = __half22float2(h[q]);
            s[q].x += f.x; s[q].y += f.y;
        }
    }
    __half2 o0 = __floats2half2_rn(s[0].x, s[0].y);
    __half2 o1 = __floats2half2_rn(s[1].x, s[1].y);
    __half2 o2 = __floats2half2_rn(s[2].x, s[2].y);
    __half2 o3 = __floats2half2_rn(s[3].x, s[3].y);
    *(uint4*)(g_T + off) = make_uint4(*(uint32_t*)&o0, *(uint32_t*)&o1,
                                      *(uint32_t*)&o2, *(uint32_t*)&o3);
}

// ========================================================================
// path: k2 (round-5 proven) — one [128M,128N] y tile
// ========================================================================
static constexpr int SM2_T    = 0;
static constexpr int SM2_U    = 16384;
static constexpr int SM2_BIAS = 32768;

__device__ void k2_path(const float* __restrict__ bias, float* __restrict__ y,
                        int bid, int mq, char* smem) {
    const uint32_t sb = smem_u32(smem);
    const int tid  = threadIdx.x;
    const int lane = tid & 31;
    const int wid  = tid >> 5;
    const int wm   = wid >> 1;
    const int wn   = wid & 1;
    const int m0   = mq * MQ + (bid >> 5) * 128;
    const int n0   = (bid & 31) * 128;

    #pragma unroll
    for (int i = 0; i < 4; i++) {
        int idx = tid + i * 256;
        int r = idx >> 3, g = idx & 7;
        uint32_t sw = SWZ((uint32_t)(r * 128 + g * 16));
        cpasync16(sb + SM2_T + sw, (const char*)g_T + (size_t)(m0 + r) * 128 + g * 16);
        cpasync16(sb + SM2_U + sw, (const char*)g_U + (size_t)(n0 + r) * 128 + g * 16);
    }
    if (tid < 32) {
        float4 bv = __ldg((const float4*)(bias + n0 + tid * 4));
        *(float4*)(smem + SM2_BIAS + tid * 16) = bv;
    }
    CP_COMMIT();
    CP_WAIT0();
    __syncthreads();

    const int sub = lane >> 3, lr = lane & 7;
    uint32_t a_off[2], b_off[4];
    #pragma unroll
    for (int mt = 0; mt < 2; mt++)
        a_off[mt] = (uint32_t)((wm * 32 + mt * 16 + (sub & 1) * 8 + lr) * 128 + (sub >> 1) * 16);
    #pragma unroll
    for (int p = 0; p < 4; p++)
        b_off[p] = (uint32_t)((wn * 64 + (p * 2 + (sub >> 1)) * 8 + lr) * 128 + (sub & 1) * 16);

    float acc[2][8][4];
    #pragma unroll
    for (int mt = 0; mt < 2; mt++)
        #pragma unroll
        for (int j = 0; j < 8; j++)
            #pragma unroll
            for (int t = 0; t < 4; t++) acc[mt][j][t] = 0.0f;

    #pragma unroll
    for (int ks = 0; ks < 4; ks++) {
        uint32_t a[2][4], b[16];
        #pragma unroll
        for (int mt = 0; mt < 2; mt++)
            ldmx4(a[mt], sb + SM2_T + SWZ(a_off[mt] + ks * 32));
        #pragma unroll
        for (int p = 0; p < 4; p++)
            ldmx4(b + 4 * p, sb + SM2_U + SWZ(b_off[p] + ks * 32));
        #pragma unroll
        for (int mt = 0; mt < 2; mt++)
            #pragma unroll
            for (int j = 0; j < 8; j++)
                mma_f16(acc[mt][j], a[mt], b + 2 * j);
    }

    const int gq = lane >> 2, tig = lane & 3;
    const float* sbias = (const float*)(smem + SM2_BIAS);
    #pragma unroll
    for (int mt = 0; mt < 2; mt++) {
        #pragma unroll
        for (int j = 0; j < 8; j++) {
            int colr = wn * 64 + j * 8 + tig * 2;
            float b0 = sbias[colr], b1 = sbias[colr + 1];
            int row = m0 + wm * 32 + mt * 16 + gq;
            *(float2*)(y + (size_t)row * OUT_F + n0 + colr) =
                make_float2(acc[mt][j][0] + b0, acc[mt][j][1] + b1);
            *(float2*)(y + (size_t)(row + 8) * OUT_F + n0 + colr) =
                make_float2(acc[mt][j][2] + b0, acc[mt][j][3] + b1);
        }
    }
}

// ========================================================================
// fused dispatcher: [k2 blocks][k1 blocks][k1r blocks]
// ========================================================================
__global__ void __launch_bounds__(256) k_fused(
    const float* __restrict__ x, const float* __restrict__ bias,
    float* __restrict__ y,
    int n_k2, int q_k2, int n_k1, int q_k1, int n_k1r, int q_k1r)
{
    extern __shared__ char smem[];
    int b = blockIdx.x;
    if (b < n_k2) {
        k2_path(bias, y, b, q_k2, smem);
    } else if (b < n_k2 + n_k1) {
        k1_path(x, b - n_k2, q_k1, smem);
    } else {
        k1r_path(b - n_k2 - n_k1, q_k1r);
    }
}

// ========================================================================
// launch: software-pipelined quarters
// ========================================================================
extern "C" void kernel_launch(void* const* d_in, const int* in_sizes, int n_in,
                              void* d_out, int out_size) {
    const float* x    = (const float*)d_in[0];
    const float* U    = (const float*)d_in[1];
    const float* V    = (const float*)d_in[2];
    const float* bias = (const float*)d_in[3];
    float* y = (float*)d_out;

    cudaFuncSetAttribute(k_fused, cudaFuncAttributeMaxDynamicSharedMemorySize, SM_FUSED);

    const int NK1  = (MQ / 128) * KSPLIT;        // 128 k1 CTAs per quarter
    const int NK1R = (MQ * RANK) / (8 * 256);    // 64 k1r CTAs per quarter
    const int NK2  = (MQ / 128) * (OUT_F / 128); // 512 k2 CTAs per quarter

    k0_prep<<<256, 256>>>(U, V);
    // L1: k1(q0)
    k_fused<<<NK1, 256, SM_FUSED>>>(x, bias, y, 0, 0, NK1, 0, 0, 0);
    // L2: k1(q1) + k1r(q0)
    k_fused<<<NK1 + NK1R, 256, SM_FUSED>>>(x, bias, y, 0, 0, NK1, 1, NK1R, 0);
    // L3: k2(q0) + k1(q2) + k1r(q1)
    k_fused<<<NK2 + NK1 + NK1R, 256, SM_FUSED>>>(x, bias, y, NK2, 0, NK1, 2, NK1R, 1);
    // L4: k2(q1) + k1(q3) + k1r(q2)
    k_fused<<<NK2 + NK1 + NK1R, 256, SM_FUSED>>>(x, bias, y, NK2, 1, NK1, 3, NK1R, 2);
    // L5: k2(q2) + k1r(q3)
    k_fused<<<NK2 + NK1R, 256, SM_FUSED>>>(x, bias, y, NK2, 2, 0, 0, NK1R, 3);
    // L6: k2(q3)
    k_fused<<<NK2, 256, SM_FUSED>>>(x, bias, y, NK2, 3, 0, 0, 0, 0);
}

// round 13
// speedup vs baseline: 1.4698x; 1.4698x over previous
#include <cuda_runtime.h>
#include <cuda_fp16.h>
#include <cstdint>

#define M_TOTAL 8192
#define IN_F    4096
#define OUT_F   4096
#define RANK    64
#define KSPLIT  8

// ---------------- device scratch ----------------
__device__ __align__(16) __half g_Tp[KSPLIT * M_TOTAL * RANK]; // partials fp16
__device__ __align__(16) __half g_T[M_TOTAL * RANK];           // reduced fp16
__device__ __align__(16) __half g_U[OUT_F * RANK];             // fp16
__device__ __align__(16) __half g_V[IN_F * RANK];              // fp16

// ---------------- helpers ----------------
__device__ __forceinline__ uint32_t smem_u32(const void* p) {
    uint32_t a;
    asm("{ .reg .u64 t; cvta.to.shared.u64 t, %1; cvt.u32.u64 %0, t; }" : "=r"(a) : "l"(p));
    return a;
}
#define SWZ(o) ((o) ^ (((o) >> 3) & 0x70))

__device__ __forceinline__ void cpasync16(uint32_t dst, const void* src) {
    asm volatile("cp.async.cg.shared.global [%0], [%1], 16;"
                 :: "r"(dst), "l"(__cvta_generic_to_global(src)) : "memory");
}
#define CP_COMMIT() asm volatile("cp.async.commit_group;" ::: "memory")
#define CP_WAIT0()  asm volatile("cp.async.wait_group 0;" ::: "memory")

__device__ __forceinline__ void ldmx4(uint32_t* r, uint32_t addr) {
    asm volatile("ldmatrix.sync.aligned.m8n8.x4.shared.b16 {%0,%1,%2,%3}, [%4];"
                 : "=r"(r[0]), "=r"(r[1]), "=r"(r[2]), "=r"(r[3]) : "r"(addr));
}
__device__ __forceinline__ void ldmx4t(uint32_t* r, uint32_t addr) {
    asm volatile("ldmatrix.sync.aligned.m8n8.x4.trans.shared.b16 {%0,%1,%2,%3}, [%4];"
                 : "=r"(r[0]), "=r"(r[1]), "=r"(r[2]), "=r"(r[3]) : "r"(addr));
}
__device__ __forceinline__ void mma_f16(float* d, const uint32_t* a, const uint32_t* b) {
    asm volatile(
        "mma.sync.aligned.m16n8k16.row.col.f32.f16.f16.f32 "
        "{%0,%1,%2,%3}, {%4,%5,%6,%7}, {%8,%9}, {%0,%1,%2,%3};"
        : "+f"(d[0]), "+f"(d[1]), "+f"(d[2]), "+f"(d[3])
        : "r"(a[0]), "r"(a[1]), "r"(a[2]), "r"(a[3]), "r"(b[0]), "r"(b[1]));
}
__device__ __forceinline__ uint2 pack4h(const float4& a) {
    __half2 h0 = __floats2half2_rn(a.x, a.y);
    __half2 h1 = __floats2half2_rn(a.z, a.w);
    return make_uint2(*(uint32_t*)&h0, *(uint32_t*)&h1);
}

// ========================================================================
// Kernel 0: convert U, V -> fp16 ([4096][64] layout). 65536 threads.
// ========================================================================
__global__ void __launch_bounds__(256) k0_prep(const float* __restrict__ U,
                                               const float* __restrict__ V) {
    int t = blockIdx.x * 256 + threadIdx.x;      // 0..65535
    size_t off = (size_t)t * 4;
    {
        float4 a = __ldg((const float4*)(U + off));
        *(uint2*)(g_U + off) = pack4h(a);
    }
    {
        float4 a = __ldg((const float4*)(V + off));
        *(uint2*)(g_V + off) = pack4h(a);
    }
}

// ========================================================================
// Kernel 1 (round-8 proven + streaming hints): Tp[s] = x[:, ksp] @ V[ksp]
// CTA tile [128M, 64N], K=512/split, grid 512, 256 threads, 8 warps,
// warp tile 32x32. Double-buffered: x LDG.CS->STS, V cp.async.
// ========================================================================
static constexpr int S1_A = 0, S1_B = 16384;
static constexpr int S1_STAGE = 24576;           // A 16KB + B 8KB
static constexpr int SM1_TOTAL = 2 * S1_STAGE;   // 49152

__global__ void __launch_bounds__(256) k1_gemm1(const float* __restrict__ x) {
    extern __shared__ char smem[];
    const uint32_t sb = smem_u32(smem);
    const int tid  = threadIdx.x;
    const int lane = tid & 31;
    const int wid  = tid >> 5;       // 0..7
    const int wm   = wid >> 1;       // 0..3 (32-row slabs)
    const int wn   = wid & 1;        // 0..1 (32-col slabs)
    const int m0   = (blockIdx.x >> 3) * 128;
    const int ksp  = blockIdx.x & 7;
    const int k0   = ksp * (IN_F / KSPLIT);      // multiples of 512

    const int sub = lane >> 3, lr = lane & 7;
    uint32_t a_off[2];
    #pragma unroll
    for (int mt = 0; mt < 2; mt++)
        a_off[mt] = (uint32_t)((wm * 32 + mt * 16 + (sub & 1) * 8 + lr) * 128 + (sub >> 1) * 16);
    const uint32_t bt_off = (uint32_t)(((sub & 1) * 8 + lr) * 128 + wn * 64 + (sub >> 1) * 16);

    float acc[2][4][4];
    #pragma unroll
    for (int mt = 0; mt < 2; mt++)
        #pragma unroll
        for (int j = 0; j < 4; j++)
            #pragma unroll
            for (int t = 0; t < 4; t++) acc[mt][j][t] = 0.0f;

    float4 xa[8];

    auto ldg_x = [&](int c) {
        #pragma unroll
        for (int i = 0; i < 8; i++) {
            int idx = tid + i * 256;
            int r = idx >> 4, q = idx & 15;
            // streaming: each x element read by exactly one CTA
            xa[i] = __ldcs((const float4*)(x + (size_t)(m0 + r) * IN_F + k0 + c * 64 + q * 4));
        }
    };
    auto sts_x = [&](int stg) {
        char* st = smem + stg * S1_STAGE;
        #pragma unroll
        for (int i = 0; i < 8; i++) {
            int idx = tid + i * 256;
            int r = idx >> 4, q = idx & 15;
            *(uint2*)(st + S1_A + SWZ((uint32_t)(r * 128 + q * 8))) = pack4h(xa[i]);
        }
    };
    auto cp_v = [&](int c, int stg) {
        uint32_t dst = sb + stg * S1_STAGE + S1_B;
        #pragma unroll
        for (int i = 0; i < 2; i++) {
            int idx = tid + i * 256;
            int r = idx >> 3, g = idx & 7;
            cpasync16(dst + SWZ((uint32_t)(r * 128 + g * 16)),
                      (const char*)g_V + (size_t)(k0 + c * 64 + r) * 128 + g * 16);
        }
        CP_COMMIT();
    };

    const int NCHUNK = (IN_F / KSPLIT) / 64;     // 8

    cp_v(0, 0);
    ldg_x(0);
    sts_x(0);
    CP_WAIT0();
    __syncthreads();

    for (int c = 0; c < NCHUNK; c++) {
        const int buf = c & 1;
        const int nbuf = buf ^ 1;

        if (c + 1 < NCHUNK) {
            cp_v(c + 1, nbuf);
            ldg_x(c + 1);
        }

        const uint32_t sbuf = sb + buf * S1_STAGE;
        #pragma unroll
        for (int ks = 0; ks < 4; ks++) {
            uint32_t a[2][4], b[8];
            #pragma unroll
            for (int mt = 0; mt < 2; mt++)
                ldmx4(a[mt], sbuf + S1_A + SWZ(a_off[mt] + ks * 32));
            ldmx4t(b,     sbuf + S1_B + SWZ(bt_off + ks * 16 * 128));
            ldmx4t(b + 4, sbuf + S1_B + SWZ(bt_off + ks * 16 * 128 + 32));
            #pragma unroll
            for (int mt = 0; mt < 2; mt++)
                #pragma unroll
                for (int j = 0; j < 4; j++)
                    mma_f16(acc[mt][j], a[mt], b + 2 * j);
        }

        if (c + 1 < NCHUNK) {
            sts_x(nbuf);
            CP_WAIT0();
        }
        __syncthreads();
    }

    // ---- epilogue: acc -> fp16 -> g_Tp[ksp] (streaming stores) ----
    __half* Tp = g_Tp + (size_t)ksp * (M_TOTAL * RANK);
    const int gq = lane >> 2, tig = lane & 3;
    #pragma unroll
    for (int mt = 0; mt < 2; mt++) {
        #pragma unroll
        for (int j = 0; j < 4; j++) {
            int col  = wn * 32 + j * 8 + tig * 2;
            int row0 = m0 + wm * 32 + mt * 16 + gq;
            __half2 v0 = __floats2half2_rn(acc[mt][j][0], acc[mt][j][1]);
            __half2 v1 = __floats2half2_rn(acc[mt][j][2], acc[mt][j][3]);
            __stcs((unsigned int*)(Tp + (size_t)row0 * RANK + col), *(unsigned int*)&v0);
            __stcs((unsigned int*)(Tp + (size_t)(row0 + 8) * RANK + col), *(unsigned int*)&v1);
        }
    }
}

// ========================================================================
// Kernel 1r: g_T = sum_s g_Tp[s]   (streaming partial reads)
// ========================================================================
__global__ void __launch_bounds__(256) k1_reduce() {
    int t = blockIdx.x * 256 + threadIdx.x;      // 0..65535
    size_t off = (size_t)t * 8;
    float2 s[4] = {{0,0},{0,0},{0,0},{0,0}};
    #pragma unroll
    for (int p = 0; p < KSPLIT; p++) {
        uint4 v = __ldcs((const uint4*)(g_Tp + (size_t)p * (M_TOTAL * RANK) + off));
        const __half2* h = (const __half2*)&v;
        #pragma unroll
        for (int q = 0; q < 4; q++) {
            float2 f = __half22float2(h[q]);
            s[q].x += f.x; s[q].y += f.y;
        }
    }
    __half2 o0 = __floats2half2_rn(s[0].x, s[0].y);
    __half2 o1 = __floats2half2_rn(s[1].x, s[1].y);
    __half2 o2 = __floats2half2_rn(s[2].x, s[2].y);
    __half2 o3 = __floats2half2_rn(s[3].x, s[3].y);
    *(uint4*)(g_T + off) = make_uint4(*(uint32_t*)&o0, *(uint32_t*)&o1,
                                      *(uint32_t*)&o2, *(uint32_t*)&o3);
}

// ========================================================================
// Kernel 2 (round-5 proven + streaming y stores): y = T @ U^T + bias
// CTA [128M,128N], K=64, grid 2048, 256 threads, warp tile 32x64.
// ========================================================================
static constexpr int SM2_T    = 0;
static constexpr int SM2_U    = 16384;
static constexpr int SM2_BIAS = 32768;
static constexpr int SM2_TOTAL = 32768 + 512;

__global__ void __launch_bounds__(256) k2_gemm2(const float* __restrict__ bias,
                                                float* __restrict__ y) {
    extern __shared__ char smem[];
    const uint32_t sb = smem_u32(smem);
    const int tid  = threadIdx.x;
    const int lane = tid & 31;
    const int wid  = tid >> 5;
    const int wm   = wid >> 1;
    const int wn   = wid & 1;
    const int m0   = (blockIdx.x >> 5) * 128;
    const int n0   = (blockIdx.x & 31) * 128;

    #pragma unroll
    for (int i = 0; i < 4; i++) {
        int idx = tid + i * 256;
        int r = idx >> 3, g = idx & 7;
        uint32_t sw = SWZ((uint32_t)(r * 128 + g * 16));
        cpasync16(sb + SM2_T + sw, (const char*)g_T + (size_t)(m0 + r) * 128 + g * 16);
        cpasync16(sb + SM2_U + sw, (const char*)g_U + (size_t)(n0 + r) * 128 + g * 16);
    }
    if (tid < 32) {
        float4 bv = __ldg((const float4*)(bias + n0 + tid * 4));
        *(float4*)(smem + SM2_BIAS + tid * 16) = bv;
    }
    CP_COMMIT();
    CP_WAIT0();
    __syncthreads();

    const int sub = lane >> 3, lr = lane & 7;
    uint32_t a_off[2], b_off[4];
    #pragma unroll
    for (int mt = 0; mt < 2; mt++)
        a_off[mt] = (uint32_t)((wm * 32 + mt * 16 + (sub & 1) * 8 + lr) * 128 + (sub >> 1) * 16);
    #pragma unroll
    for (int p = 0; p < 4; p++)
        b_off[p] = (uint32_t)((wn * 64 + (p * 2 + (sub >> 1)) * 8 + lr) * 128 + (sub & 1) * 16);

    float acc[2][8][4];
    #pragma unroll
    for (int mt = 0; mt < 2; mt++)
        #pragma unroll
        for (int j = 0; j < 8; j++)
            #pragma unroll
            for (int t = 0; t < 4; t++) acc[mt][j][t] = 0.0f;

    #pragma unroll
    for (int ks = 0; ks < 4; ks++) {
        uint32_t a[2][4], b[16];
        #pragma unroll
        for (int mt = 0; mt < 2; mt++)
            ldmx4(a[mt], sb + SM2_T + SWZ(a_off[mt] + ks * 32));
        #pragma unroll
        for (int p = 0; p < 4; p++)
            ldmx4(b + 4 * p, sb + SM2_U + SWZ(b_off[p] + ks * 32));
        #pragma unroll
        for (int mt = 0; mt < 2; mt++)
            #pragma unroll
            for (int j = 0; j < 8; j++)
                mma_f16(acc[mt][j], a[mt], b + 2 * j);
    }

    const int gq = lane >> 2, tig = lane & 3;
    const float* sbias = (const float*)(smem + SM2_BIAS);
    #pragma unroll
    for (int mt = 0; mt < 2; mt++) {
        #pragma unroll
        for (int j = 0; j < 8; j++) {
            int colr = wn * 64 + j * 8 + tig * 2;
            float b0 = sbias[colr], b1 = sbias[colr + 1];
            int row = m0 + wm * 32 + mt * 16 + gq;
            // y written once, never re-read: evict-first streaming stores
            __stcs((float2*)(y + (size_t)row * OUT_F + n0 + colr),
                   make_float2(acc[mt][j][0] + b0, acc[mt][j][1] + b1));
            __stcs((float2*)(y + (size_t)(row + 8) * OUT_F + n0 + colr),
                   make_float2(acc[mt][j][2] + b0, acc[mt][j][3] + b1));
        }
    }
}

// ========================================================================
// launch
// ========================================================================
extern "C" void kernel_launch(void* const* d_in, const int* in_sizes, int n_in,
                              void* d_out, int out_size) {
    const float* x    = (const float*)d_in[0];
    const float* U    = (const float*)d_in[1];
    const float* V    = (const float*)d_in[2];
    const float* bias = (const float*)d_in[3];
    float* y = (float*)d_out;

    cudaFuncSetAttribute(k1_gemm1, cudaFuncAttributeMaxDynamicSharedMemorySize, SM1_TOTAL);
    cudaFuncSetAttribute(k2_gemm2, cudaFuncAttributeMaxDynamicSharedMemorySize, SM2_TOTAL);

    k0_prep<<<256, 256>>>(U, V);
    k1_gemm1<<<(M_TOTAL / 128) * KSPLIT, 256, SM1_TOTAL>>>(x);
    k1_reduce<<<256, 256>>>();
    k2_gemm2<<<(M_TOTAL / 128) * (OUT_F / 128), 256, SM2_TOTAL>>>(bias, y);
}

// round 14
// speedup vs baseline: 1.4727x; 1.0019x over previous
#include <cuda_runtime.h>
#include <cuda_fp16.h>
#include <cstdint>

#define M_TOTAL 8192
#define IN_F    4096
#define OUT_F   4096
#define RANK    64
#define KSPLIT  8

// ---------------- device scratch ----------------
__device__ __align__(16) __half g_Tp[KSPLIT * M_TOTAL * RANK]; // partials fp16
__device__ __align__(16) __half g_T[M_TOTAL * RANK];           // reduced fp16
__device__ __align__(16) __half g_U[OUT_F * RANK];             // fp16
__device__ __align__(16) __half g_V[IN_F * RANK];              // fp16

// ---------------- helpers ----------------
__device__ __forceinline__ uint32_t smem_u32(const void* p) {
    uint32_t a;
    asm("{ .reg .u64 t; cvta.to.shared.u64 t, %1; cvt.u32.u64 %0, t; }" : "=r"(a) : "l"(p));
    return a;
}
#define SWZ(o) ((o) ^ (((o) >> 3) & 0x70))

__device__ __forceinline__ void cpasync16(uint32_t dst, const void* src) {
    asm volatile("cp.async.cg.shared.global [%0], [%1], 16;"
                 :: "r"(dst), "l"(__cvta_generic_to_global(src)) : "memory");
}
#define CP_COMMIT() asm volatile("cp.async.commit_group;" ::: "memory")
#define CP_WAIT0()  asm volatile("cp.async.wait_group 0;" ::: "memory")
#define CP_WAIT(n)  asm volatile("cp.async.wait_group %0;" :: "n"(n) : "memory")

__device__ __forceinline__ void ldmx4(uint32_t* r, uint32_t addr) {
    asm volatile("ldmatrix.sync.aligned.m8n8.x4.shared.b16 {%0,%1,%2,%3}, [%4];"
                 : "=r"(r[0]), "=r"(r[1]), "=r"(r[2]), "=r"(r[3]) : "r"(addr));
}
__device__ __forceinline__ void ldmx4t(uint32_t* r, uint32_t addr) {
    asm volatile("ldmatrix.sync.aligned.m8n8.x4.trans.shared.b16 {%0,%1,%2,%3}, [%4];"
                 : "=r"(r[0]), "=r"(r[1]), "=r"(r[2]), "=r"(r[3]) : "r"(addr));
}
__device__ __forceinline__ void mma_f16(float* d, const uint32_t* a, const uint32_t* b) {
    asm volatile(
        "mma.sync.aligned.m16n8k16.row.col.f32.f16.f16.f32 "
        "{%0,%1,%2,%3}, {%4,%5,%6,%7}, {%8,%9}, {%0,%1,%2,%3};"
        : "+f"(d[0]), "+f"(d[1]), "+f"(d[2]), "+f"(d[3])
        : "r"(a[0]), "r"(a[1]), "r"(a[2]), "r"(a[3]), "r"(b[0]), "r"(b[1]));
}
__device__ __forceinline__ uint2 pack4h(const float4& a) {
    __half2 h0 = __floats2half2_rn(a.x, a.y);
    __half2 h1 = __floats2half2_rn(a.z, a.w);
    return make_uint2(*(uint32_t*)&h0, *(uint32_t*)&h1);
}

// ========================================================================
// Kernel 0: convert U, V -> fp16 ([4096][64] layout). 65536 threads.
// ========================================================================
__global__ void __launch_bounds__(256) k0_prep(const float* __restrict__ U,
                                               const float* __restrict__ V) {
    int t = blockIdx.x * 256 + threadIdx.x;      // 0..65535
    size_t off = (size_t)t * 4;
    {
        float4 a = __ldg((const float4*)(U + off));
        *(uint2*)(g_U + off) = pack4h(a);
    }
    {
        float4 a = __ldg((const float4*)(V + off));
        *(uint2*)(g_V + off) = pack4h(a);
    }
}

// ========================================================================
// Kernel 1 (round-13 proven): Tp[s] = x[:, ksp] @ V[ksp]
// CTA tile [128M, 64N], K=512/split, grid 512, 256 threads, 8 warps,
// warp tile 32x32. Double-buffered: x LDG.CS->STS, V cp.async.
// ========================================================================
static constexpr int S1_A = 0, S1_B = 16384;
static constexpr int S1_STAGE = 24576;           // A 16KB + B 8KB
static constexpr int SM1_TOTAL = 2 * S1_STAGE;   // 49152

__global__ void __launch_bounds__(256) k1_gemm1(const float* __restrict__ x) {
    extern __shared__ char smem[];
    const uint32_t sb = smem_u32(smem);
    const int tid  = threadIdx.x;
    const int lane = tid & 31;
    const int wid  = tid >> 5;       // 0..7
    const int wm   = wid >> 1;       // 0..3 (32-row slabs)
    const int wn   = wid & 1;        // 0..1 (32-col slabs)
    const int m0   = (blockIdx.x >> 3) * 128;
    const int ksp  = blockIdx.x & 7;
    const int k0   = ksp * (IN_F / KSPLIT);      // multiples of 512

    const int sub = lane >> 3, lr = lane & 7;
    uint32_t a_off[2];
    #pragma unroll
    for (int mt = 0; mt < 2; mt++)
        a_off[mt] = (uint32_t)((wm * 32 + mt * 16 + (sub & 1) * 8 + lr) * 128 + (sub >> 1) * 16);
    const uint32_t bt_off = (uint32_t)(((sub & 1) * 8 + lr) * 128 + wn * 64 + (sub >> 1) * 16);

    float acc[2][4][4];
    #pragma unroll
    for (int mt = 0; mt < 2; mt++)
        #pragma unroll
        for (int j = 0; j < 4; j++)
            #pragma unroll
            for (int t = 0; t < 4; t++) acc[mt][j][t] = 0.0f;

    float4 xa[8];

    auto ldg_x = [&](int c) {
        #pragma unroll
        for (int i = 0; i < 8; i++) {
            int idx = tid + i * 256;
            int r = idx >> 4, q = idx & 15;
            xa[i] = __ldcs((const float4*)(x + (size_t)(m0 + r) * IN_F + k0 + c * 64 + q * 4));
        }
    };
    auto sts_x = [&](int stg) {
        char* st = smem + stg * S1_STAGE;
        #pragma unroll
        for (int i = 0; i < 8; i++) {
            int idx = tid + i * 256;
            int r = idx >> 4, q = idx & 15;
            *(uint2*)(st + S1_A + SWZ((uint32_t)(r * 128 + q * 8))) = pack4h(xa[i]);
        }
    };
    auto cp_v = [&](int c, int stg) {
        uint32_t dst = sb + stg * S1_STAGE + S1_B;
        #pragma unroll
        for (int i = 0; i < 2; i++) {
            int idx = tid + i * 256;
            int r = idx >> 3, g = idx & 7;
            cpasync16(dst + SWZ((uint32_t)(r * 128 + g * 16)),
                      (const char*)g_V + (size_t)(k0 + c * 64 + r) * 128 + g * 16);
        }
        CP_COMMIT();
    };

    const int NCHUNK = (IN_F / KSPLIT) / 64;     // 8

    cp_v(0, 0);
    ldg_x(0);
    sts_x(0);
    CP_WAIT0();
    __syncthreads();

    for (int c = 0; c < NCHUNK; c++) {
        const int buf = c & 1;
        const int nbuf = buf ^ 1;

        if (c + 1 < NCHUNK) {
            cp_v(c + 1, nbuf);
            ldg_x(c + 1);
        }

        const uint32_t sbuf = sb + buf * S1_STAGE;
        #pragma unroll
        for (int ks = 0; ks < 4; ks++) {
            uint32_t a[2][4], b[8];
            #pragma unroll
            for (int mt = 0; mt < 2; mt++)
                ldmx4(a[mt], sbuf + S1_A + SWZ(a_off[mt] + ks * 32));
            ldmx4t(b,     sbuf + S1_B + SWZ(bt_off + ks * 16 * 128));
            ldmx4t(b + 4, sbuf + S1_B + SWZ(bt_off + ks * 16 * 128 + 32));
            #pragma unroll
            for (int mt = 0; mt < 2; mt++)
                #pragma unroll
                for (int j = 0; j < 4; j++)
                    mma_f16(acc[mt][j], a[mt], b + 2 * j);
        }

        if (c + 1 < NCHUNK) {
            sts_x(nbuf);
            CP_WAIT0();
        }
        __syncthreads();
    }

    // ---- epilogue: acc -> fp16 -> g_Tp[ksp] (streaming stores) ----
    __half* Tp = g_Tp + (size_t)ksp * (M_TOTAL * RANK);
    const int gq = lane >> 2, tig = lane & 3;
    #pragma unroll
    for (int mt = 0; mt < 2; mt++) {
        #pragma unroll
        for (int j = 0; j < 4; j++) {
            int col  = wn * 32 + j * 8 + tig * 2;
            int row0 = m0 + wm * 32 + mt * 16 + gq;
            __half2 v0 = __floats2half2_rn(acc[mt][j][0], acc[mt][j][1]);
            __half2 v1 = __floats2half2_rn(acc[mt][j][2], acc[mt][j][3]);
            __stcs((unsigned int*)(Tp + (size_t)row0 * RANK + col), *(unsigned int*)&v0);
            __stcs((unsigned int*)(Tp + (size_t)(row0 + 8) * RANK + col), *(unsigned int*)&v1);
        }
    }
}

// ========================================================================
// Kernel 1r: g_T = sum_s g_Tp[s]   (streaming partial reads)
// ========================================================================
__global__ void __launch_bounds__(256) k1_reduce() {
    int t = blockIdx.x * 256 + threadIdx.x;      // 0..65535
    size_t off = (size_t)t * 8;
    float2 s[4] = {{0,0},{0,0},{0,0},{0,0}};
    #pragma unroll
    for (int p = 0; p < KSPLIT; p++) {
        uint4 v = __ldcs((const uint4*)(g_Tp + (size_t)p * (M_TOTAL * RANK) + off));
        const __half2* h = (const __half2*)&v;
        #pragma unroll
        for (int q = 0; q < 4; q++) {
            float2 f = __half22float2(h[q]);
            s[q].x += f.x; s[q].y += f.y;
        }
    }
    __half2 o0 = __floats2half2_rn(s[0].x, s[0].y);
    __half2 o1 = __floats2half2_rn(s[1].x, s[1].y);
    __half2 o2 = __floats2half2_rn(s[2].x, s[2].y);
    __half2 o3 = __floats2half2_rn(s[3].x, s[3].y);
    *(uint4*)(g_T + off) = make_uint4(*(uint32_t*)&o0, *(uint32_t*)&o1,
                                      *(uint32_t*)&o2, *(uint32_t*)&o3);
}

// ========================================================================
// Kernel 2: y = T @ U^T + bias
// CTA tile [256M, 128N] as two sequential 128M halves sharing one U tile.
// grid 1024, 256 threads, warp tile 32x64, acc registers reused per half.
// T1 cp.async'd in prologue (separate group), lands during half-0 compute.
// ========================================================================
static constexpr int SM2_T0   = 0;
static constexpr int SM2_T1   = 16384;
static constexpr int SM2_U    = 32768;
static constexpr int SM2_BIAS = 49152;
static constexpr int SM2_TOTAL = 49152 + 512;

__global__ void __launch_bounds__(256) k2_gemm2(const float* __restrict__ bias,
                                                float* __restrict__ y) {
    extern __shared__ char smem[];
    const uint32_t sb = smem_u32(smem);
    const int tid  = threadIdx.x;
    const int lane = tid & 31;
    const int wid  = tid >> 5;
    const int wm   = wid >> 1;
    const int wn   = wid & 1;
    const int m0   = (blockIdx.x >> 5) * 256;
    const int n0   = (blockIdx.x & 31) * 128;

    // ---- prologue: group A = T0 + U; group B = T1 ----
    #pragma unroll
    for (int i = 0; i < 4; i++) {
        int idx = tid + i * 256;
        int r = idx >> 3, g = idx & 7;
        uint32_t sw = SWZ((uint32_t)(r * 128 + g * 16));
        cpasync16(sb + SM2_T0 + sw, (const char*)g_T + (size_t)(m0 + r) * 128 + g * 16);
        cpasync16(sb + SM2_U + sw, (const char*)g_U + (size_t)(n0 + r) * 128 + g * 16);
    }
    CP_COMMIT();
    #pragma unroll
    for (int i = 0; i < 4; i++) {
        int idx = tid + i * 256;
        int r = idx >> 3, g = idx & 7;
        uint32_t sw = SWZ((uint32_t)(r * 128 + g * 16));
        cpasync16(sb + SM2_T1 + sw, (const char*)g_T + (size_t)(m0 + 128 + r) * 128 + g * 16);
    }
    CP_COMMIT();
    if (tid < 32) {
        float4 bv = __ldg((const float4*)(bias + n0 + tid * 4));
        *(float4*)(smem + SM2_BIAS + tid * 16) = bv;
    }
    CP_WAIT(1);               // T0 + U ready; T1 still in flight
    __syncthreads();

    const int sub = lane >> 3, lr = lane & 7;
    uint32_t a_off[2], b_off[4];
    #pragma unroll
    for (int mt = 0; mt < 2; mt++)
        a_off[mt] = (uint32_t)((wm * 32 + mt * 16 + (sub & 1) * 8 + lr) * 128 + (sub >> 1) * 16);
    #pragma unroll
    for (int p = 0; p < 4; p++)
        b_off[p] = (uint32_t)((wn * 64 + (p * 2 + (sub >> 1)) * 8 + lr) * 128 + (sub & 1) * 16);

    const int gq = lane >> 2, tig = lane & 3;
    const float* sbias = (const float*)(smem + SM2_BIAS);

    #pragma unroll
    for (int mh = 0; mh < 2; mh++) {
        const uint32_t tb = sb + (mh == 0 ? SM2_T0 : SM2_T1);

        float acc[2][8][4];
        #pragma unroll
        for (int mt = 0; mt < 2; mt++)
            #pragma unroll
            for (int j = 0; j < 8; j++)
                #pragma unroll
                for (int t = 0; t < 4; t++) acc[mt][j][t] = 0.0f;

        #pragma unroll
        for (int ks = 0; ks < 4; ks++) {
            uint32_t a[2][4], b[16];
            #pragma unroll
            for (int mt = 0; mt < 2; mt++)
                ldmx4(a[mt], tb + SWZ(a_off[mt] + ks * 32));
            #pragma unroll
            for (int p = 0; p < 4; p++)
                ldmx4(b + 4 * p, sb + SM2_U + SWZ(b_off[p] + ks * 32));
            #pragma unroll
            for (int mt = 0; mt < 2; mt++)
                #pragma unroll
                for (int j = 0; j < 8; j++)
                    mma_f16(acc[mt][j], a[mt], b + 2 * j);
        }

        #pragma unroll
        for (int mt = 0; mt < 2; mt++) {
            #pragma unroll
            for (int j = 0; j < 8; j++) {
                int colr = wn * 64 + j * 8 + tig * 2;
                float b0 = sbias[colr], b1 = sbias[colr + 1];
                int row = m0 + mh * 128 + wm * 32 + mt * 16 + gq;
                __stcs((float2*)(y + (size_t)row * OUT_F + n0 + colr),
                       make_float2(acc[mt][j][0] + b0, acc[mt][j][1] + b1));
                __stcs((float2*)(y + (size_t)(row + 8) * OUT_F + n0 + colr),
                       make_float2(acc[mt][j][2] + b0, acc[mt][j][3] + b1));
            }
        }

        if (mh == 0) {
            CP_WAIT(0);       // T1 landed (issued in prologue)
            __syncthreads();
        }
    }
}

// ========================================================================
// launch
// ========================================================================
extern "C" void kernel_launch(void* const* d_in, const int* in_sizes, int n_in,
                              void* d_out, int out_size) {
    const float* x    = (const float*)d_in[0];
    const float* U    = (const float*)d_in[1];
    const float* V    = (const float*)d_in[2];
    const float* bias = (const float*)d_in[3];
    float* y = (float*)d_out;

    cudaFuncSetAttribute(k1_gemm1, cudaFuncAttributeMaxDynamicSharedMemorySize, SM1_TOTAL);
    cudaFuncSetAttribute(k2_gemm2, cudaFuncAttributeMaxDynamicSharedMemorySize, SM2_TOTAL);

    k0_prep<<<256, 256>>>(U, V);
    k1_gemm1<<<(M_TOTAL / 128) * KSPLIT, 256, SM1_TOTAL>>>(x);
    k1_reduce<<<256, 256>>>();
    k2_gemm2<<<(M_TOTAL / 256) * (OUT_F / 128), 256, SM2_TOTAL>>>(bias, y);
}